// round 17
// baseline (speedup 1.0000x reference)
#include <cuda_runtime.h>
#include <math.h>

// Problem constants
#define N_IMG 4
#define C_DIM 256
#define H_DIM 50
#define W_DIM 50
#define HW (H_DIM * W_DIM)
#define PH 7
#define PW 7
#define NBINS (PH * PW)
#define N_ROI 1024
#define OUT_PER_ROI (C_DIM * NBINS)   // 12544 floats
#define SPATIAL_SCALE 0.0625f
#define ROW_STRIDE (W_DIM * C_DIM)    // floats per h-row (within a level)
#define LVL_STRIDE (N_IMG * HW * C_DIM)   // floats per sparse-table level

// fl(1/7) in fp32 — XLA rewrites (x / 7) into (x * fl(1/7)); we must match it.
#define RCP_7 0.14285714924335479736328125f

// Sparse range-max table, 4 levels. Level 0 = transposed input (NHWC).
// T_k[n][h][w][c] = max over w' in [w, w+2^k) of x_nhwc. 40.96 MB.
__device__ float g_tab[4 * LVL_STRIDE];

// Precomputed per-roi geometry (exact XLA numerics, computed once)
__device__ int  g_boff[N_ROI];        // image offset within a level (floats)
__device__ int  g_hs[N_ROI * PH];
__device__ int  g_he[N_ROI * PH];
__device__ int2 g_off[N_ROI * PW];    // (offA, offB) = level+column float offsets
                                      // offA < 0 marks an empty w-window

// ---------------------------------------------------------------------------
// FUSED transpose + sparse-table build (unchanged from R16, proven).
// One block per (h, img, 32-ch strip): grid = (50, 4, 8), block = 256.
// Block (0,0,0) also precomputes all roi bin edges + lookup offsets.
// ---------------------------------------------------------------------------
__global__ void __launch_bounds__(256) buildtab_kernel(const float* __restrict__ x,
                                                       const float* __restrict__ rois) {
    __shared__ float tile[32][51];   // [c_local][w], pad 51: gcd(51,32)=1

    if (blockIdx.x == 0 && blockIdx.y == 0 && blockIdx.z == 0) {
        const int tid = threadIdx.x;
        #pragma unroll
        for (int q = 0; q < 4; ++q) {
            const int roi = tid * 4 + q;   // 0..1023
            const float* r = rois + roi * 5;
            const int b  = (int)r[0];
            const int xs = (int)rintf(__fmul_rn(r[1], SPATIAL_SCALE));
            const int ys = (int)rintf(__fmul_rn(r[2], SPATIAL_SCALE));
            const int xe = (int)rintf(__fmul_rn(r[3], SPATIAL_SCALE));
            const int ye = (int)rintf(__fmul_rn(r[4], SPATIAL_SCALE));
            const float rw = (float)max(xe - xs + 1, 1);
            const float rh = (float)max(ye - ys + 1, 1);
            const float bh = __fmul_rn(rh, RCP_7);   // XLA reciprocal-multiply
            const float bw = __fmul_rn(rw, RCP_7);

            g_boff[roi] = b * (HW * C_DIM);
            #pragma unroll
            for (int p = 0; p < PH; ++p) {
                int hs = (int)floorf(__fmul_rn((float)p,        bh)) + ys;
                int he = (int)ceilf (__fmul_rn((float)p + 1.0f, bh)) + ys;
                int ws = (int)floorf(__fmul_rn((float)p,        bw)) + xs;
                int we = (int)ceilf (__fmul_rn((float)p + 1.0f, bw)) + xs;
                hs = min(max(hs, 0), H_DIM);
                he = min(max(he, 0), H_DIM);
                ws = min(max(ws, 0), W_DIM);
                we = min(max(we, 0), W_DIM);
                g_hs[roi * PH + p] = hs;
                g_he[roi * PH + p] = he;

                const int span = we - ws;   // <= 9; <=0 means empty
                if (span >= 1) {
                    const int k = 31 - __clz(span);   // floor(log2(span)), 0..3
                    g_off[roi * PW + p] =
                        make_int2(k * LVL_STRIDE + ws * C_DIM,
                                  k * LVL_STRIDE + (we - (1 << k)) * C_DIM);
                } else {
                    g_off[roi * PW + p] = make_int2(-1, -1);
                }
            }
        }
    }

    const int h  = blockIdx.x;
    const int n  = blockIdx.y;
    const int c0 = blockIdx.z * 32;

    // Load NCHW tile: 32 c-rows of 50 contiguous floats each.
    #pragma unroll 1
    for (int i = threadIdx.x; i < 32 * W_DIM; i += 256) {
        const int c = i / W_DIM;
        const int w = i - c * W_DIM;
        tile[c][w] = x[((size_t)(n * C_DIM + c0 + c) * H_DIM + h) * W_DIM + w];
    }
    __syncthreads();

    const int lane = threadIdx.x & 31;   // c within strip
    const int wg   = threadIdx.x >> 5;   // 8 w-groups

    const size_t outbase = ((size_t)n * HW + (size_t)h * W_DIM) * C_DIM + c0 + lane;

    #pragma unroll 1
    for (int w = wg; w < W_DIM; w += 8) {
        const float s0 = tile[lane][w];
        g_tab[outbase + (size_t)w * C_DIM] = s0;                       // level 0

        if (w <= W_DIM - 2) {
            const float m1 = fmaxf(s0, tile[lane][w + 1]);
            g_tab[1 * LVL_STRIDE + outbase + (size_t)w * C_DIM] = m1;  // level 1

            if (w <= W_DIM - 4) {
                const float m2 = fmaxf(m1, fmaxf(tile[lane][w + 2], tile[lane][w + 3]));
                g_tab[2 * LVL_STRIDE + outbase + (size_t)w * C_DIM] = m2;  // level 2

                if (w <= W_DIM - 8) {
                    const float m3 = fmaxf(m2,
                        fmaxf(fmaxf(tile[lane][w + 4], tile[lane][w + 5]),
                              fmaxf(tile[lane][w + 6], tile[lane][w + 7])));
                    g_tab[3 * LVL_STRIDE + outbase + (size_t)w * C_DIM] = m3;  // level 3
                }
            }
        }
    }
}

// ---------------------------------------------------------------------------
// RoI max pooling via sparse-table lookups, BOTH bins fused in one h-sweep.
// One block per (roi, ph-row). Grid = 1024 x 7.
// Block = 256 = 4 pw-groups x 64 lanes (float4 -> 256 ch).
// Thread owns bins pwA = grp and pwB = grp+4 — SAME h-window, each bin is
// 2 pointer streams -> 8 independent LDG.128 per 2-row trip (MLP = 8).
// Offsets clamped to 0 for empty/invalid bins (keeps LDG.128 aligned);
// results zeroed via flags. __launch_bounds__(256,4): 64-reg headroom so
// the 8 float4 temps never serialize (R11 lesson).
// ---------------------------------------------------------------------------
__global__ void __launch_bounds__(256, 4) roipool_kernel(float* __restrict__ out) {
    __shared__ float s_out[C_DIM * PW];   // [c][pw] = 7168 B

    const int roi = blockIdx.x;
    const int ph  = blockIdx.y;

    const int boff = __ldg(&g_boff[roi]);
    const int hs   = __ldg(&g_hs[roi * PH + ph]);
    const int he   = __ldg(&g_he[roi * PH + ph]);

    const int lane = threadIdx.x & 63;   // 64 lanes -> 256 channels via float4
    const int grp  = threadIdx.x >> 6;   // 4 pw-groups
    const int c0   = lane * 4;

    const int pwA = grp;
    const int pwB = grp + 4;
    const bool hasB = (pwB < PW);

    int2 offA = __ldg(&g_off[roi * PW + pwA]);
    // for grp=3 read bin A's entry again (safe, discarded)
    int2 offB = __ldg(&g_off[roi * PW + (hasB ? pwB : pwA)]);

    const bool emptyA = (hs >= he) || (offA.x < 0);
    const bool emptyB = (hs >= he) || (offB.x < 0);
    if (offA.x < 0) offA = make_int2(0, 0);   // clamp: keep 16B alignment
    if (offB.x < 0) offB = make_int2(0, 0);

    const float* __restrict__ pA0 = g_tab + offA.x + boff + c0;
    const float* __restrict__ pA1 = g_tab + offA.y + boff + c0;
    const float* __restrict__ pB0 = g_tab + offB.x + boff + c0;
    const float* __restrict__ pB1 = g_tab + offB.y + boff + c0;

    float a0 = -INFINITY, a1 = -INFINITY, a2 = -INFINITY, a3 = -INFINITY;
    float b0 = -INFINITY, b1 = -INFINITY, b2 = -INFINITY, b3 = -INFINITY;

    int h = hs;
    #pragma unroll 1
    for (; h + 1 < he; h += 2) {          // 8 independent LDG.128 per trip
        const int r0 = h * ROW_STRIDE;
        const int r1 = r0 + ROW_STRIDE;
        const float4 va = *(const float4*)(pA0 + r0);
        const float4 vb = *(const float4*)(pA1 + r0);
        const float4 vc = *(const float4*)(pA0 + r1);
        const float4 vd = *(const float4*)(pA1 + r1);
        const float4 ve = *(const float4*)(pB0 + r0);
        const float4 vf = *(const float4*)(pB1 + r0);
        const float4 vg = *(const float4*)(pB0 + r1);
        const float4 vh = *(const float4*)(pB1 + r1);
        a0 = fmaxf(fmaxf(fmaxf(a0, va.x), vb.x), fmaxf(vc.x, vd.x));
        a1 = fmaxf(fmaxf(fmaxf(a1, va.y), vb.y), fmaxf(vc.y, vd.y));
        a2 = fmaxf(fmaxf(fmaxf(a2, va.z), vb.z), fmaxf(vc.z, vd.z));
        a3 = fmaxf(fmaxf(fmaxf(a3, va.w), vb.w), fmaxf(vc.w, vd.w));
        b0 = fmaxf(fmaxf(fmaxf(b0, ve.x), vf.x), fmaxf(vg.x, vh.x));
        b1 = fmaxf(fmaxf(fmaxf(b1, ve.y), vf.y), fmaxf(vg.y, vh.y));
        b2 = fmaxf(fmaxf(fmaxf(b2, ve.z), vf.z), fmaxf(vg.z, vh.z));
        b3 = fmaxf(fmaxf(fmaxf(b3, ve.w), vf.w), fmaxf(vg.w, vh.w));
    }
    if (h < he) {                         // remainder row: 4 loads
        const int r0 = h * ROW_STRIDE;
        const float4 va = *(const float4*)(pA0 + r0);
        const float4 vb = *(const float4*)(pA1 + r0);
        const float4 ve = *(const float4*)(pB0 + r0);
        const float4 vf = *(const float4*)(pB1 + r0);
        a0 = fmaxf(a0, fmaxf(va.x, vb.x));
        a1 = fmaxf(a1, fmaxf(va.y, vb.y));
        a2 = fmaxf(a2, fmaxf(va.z, vb.z));
        a3 = fmaxf(a3, fmaxf(va.w, vb.w));
        b0 = fmaxf(b0, fmaxf(ve.x, vf.x));
        b1 = fmaxf(b1, fmaxf(ve.y, vf.y));
        b2 = fmaxf(b2, fmaxf(ve.z, vf.z));
        b3 = fmaxf(b3, fmaxf(ve.w, vf.w));
    }

    if (emptyA) { a0 = a1 = a2 = a3 = 0.0f; }
    s_out[(c0 + 0) * PW + pwA] = a0;
    s_out[(c0 + 1) * PW + pwA] = a1;
    s_out[(c0 + 2) * PW + pwA] = a2;
    s_out[(c0 + 3) * PW + pwA] = a3;

    if (hasB) {
        if (emptyB) { b0 = b1 = b2 = b3 = 0.0f; }
        s_out[(c0 + 0) * PW + pwB] = b0;
        s_out[(c0 + 1) * PW + pwB] = b1;
        s_out[(c0 + 2) * PW + pwB] = b2;
        s_out[(c0 + 3) * PW + pwB] = b3;
    }
    __syncthreads();

    // Store: out[roi, c, ph, pw] = s_out[c*7 + pw].
    float* __restrict__ obase = out + (size_t)roi * OUT_PER_ROI + ph * PW;
    #pragma unroll 1
    for (int i = threadIdx.x; i < C_DIM * PW; i += 256) {
        const int c  = i / PW;
        const int pw = i - c * PW;
        obase[c * NBINS + pw] = s_out[i];
    }
}

extern "C" void kernel_launch(void* const* d_in, const int* in_sizes, int n_in,
                              void* d_out, int out_size) {
    const float* x    = (const float*)d_in[0];
    const float* rois = (const float*)d_in[1];
    float* out        = (float*)d_out;

    (void)in_sizes; (void)n_in; (void)out_size;

    dim3 bgrid(H_DIM, N_IMG, C_DIM / 32);   // 50 x 4 x 8 = 1600 blocks
    buildtab_kernel<<<bgrid, 256>>>(x, rois);

    dim3 pgrid(N_ROI, PH);
    roipool_kernel<<<pgrid, 256>>>(out);
}